// round 1
// baseline (speedup 1.0000x reference)
#include <cuda_runtime.h>
#include <cstddef>
#include <cstdint>

#define NND 100000
#define EE  1600000
#define RR  8
#define BB  4
#define DD  64

// Scratch (no runtime allocation allowed) ------------------------------------
__device__ float g_Ht[(size_t)RR * NND * DD];   // 204.8 MB transformed features
__device__ float g_h1[(size_t)NND * DD];        // layer-1 output (pre-relu)
__device__ float g_h2[(size_t)NND * DD];        // layer-2 output (pre-relu)

// ----------------------------------------------------------------------------
// Transform: Ht[r,n,o] = sum_b wcomp[r,b] * sum_i relu?(X[n,i]) * bases[b,i,o]
// Basis trick: compute 4 basis-GEMMs in registers, combine with wcomp at store.
// Block = 256 threads = (o:64) x (q:4 node groups of 16). Tile = 64 nodes.
// ----------------------------------------------------------------------------
__global__ void __launch_bounds__(256) transform_kernel(
    const float* __restrict__ X, const float* __restrict__ bases,
    const float* __restrict__ wcomp, float* __restrict__ Ht, int relu)
{
    extern __shared__ float sm[];
    float* bs = sm;                    // 4*64*64 = 16384 floats
    float* xs = sm + BB * DD * DD;     // 64*64   = 4096 floats
    float* wc = xs + 64 * DD;          // 32 floats

    const int tid = threadIdx.x;

    // load bases into smem (vectorized)
    {
        const float4* b4 = (const float4*)bases;
        float4* s4 = (float4*)bs;
        #pragma unroll 4
        for (int i = tid; i < BB * DD * DD / 4; i += 256) s4[i] = b4[i];
    }
    if (tid < RR * BB) wc[tid] = wcomp[tid];

    // load node tile (with fused relu on input), zero-pad past N
    const int n0 = blockIdx.x * 64;
    for (int i = tid; i < 64 * DD / 4; i += 256) {
        int n = i / (DD / 4);
        float4 v = make_float4(0.f, 0.f, 0.f, 0.f);
        if (n0 + n < NND) {
            v = ((const float4*)X)[(size_t)(n0 + n) * (DD / 4) + (i % (DD / 4))];
            if (relu) {
                v.x = fmaxf(v.x, 0.f); v.y = fmaxf(v.y, 0.f);
                v.z = fmaxf(v.z, 0.f); v.w = fmaxf(v.w, 0.f);
            }
        }
        ((float4*)xs)[i] = v;
    }
    __syncthreads();

    const int o = tid & 63;
    const int q = tid >> 6;            // node group 0..3 (16 nodes each)
    float a0[16], a1[16], a2[16], a3[16];
    #pragma unroll
    for (int n = 0; n < 16; n++) { a0[n] = a1[n] = a2[n] = a3[n] = 0.f; }

    const float* xbase = xs + q * 16 * DD;
    #pragma unroll 4
    for (int i = 0; i < DD; i++) {
        const float b0 = bs[0 * DD * DD + i * DD + o];
        const float b1 = bs[1 * DD * DD + i * DD + o];
        const float b2 = bs[2 * DD * DD + i * DD + o];
        const float b3 = bs[3 * DD * DD + i * DD + o];
        #pragma unroll
        for (int n = 0; n < 16; n++) {
            const float x = xbase[n * DD + i];   // warp-uniform broadcast
            a0[n] += x * b0; a1[n] += x * b1;
            a2[n] += x * b2; a3[n] += x * b3;
        }
    }

    // combine with wcomp and store all 8 relations
    #pragma unroll
    for (int n = 0; n < 16; n++) {
        const int node = n0 + q * 16 + n;
        if (node >= NND) break;
        #pragma unroll
        for (int r = 0; r < RR; r++) {
            const float v = wc[r * BB + 0] * a0[n] + wc[r * BB + 1] * a1[n]
                          + wc[r * BB + 2] * a2[n] + wc[r * BB + 3] * a3[n];
            Ht[((size_t)r * NND + node) * DD + o] = v;
        }
    }
}

// ----------------------------------------------------------------------------
// Edge stage: out[dst] += norm * Ht[etype*N + src].  16 threads per edge,
// one float4 per thread, vectorized reduction (red.v4) into L2-resident out.
// ----------------------------------------------------------------------------
__global__ void __launch_bounds__(256) edge_kernel(
    const float* __restrict__ Ht, const int* __restrict__ src,
    const int* __restrict__ dst, const int* __restrict__ ety,
    const float* __restrict__ norm, float* __restrict__ out)
{
    const long long gt = (long long)blockIdx.x * blockDim.x + threadIdx.x;
    const int e = (int)(gt >> 4);
    if (e >= EE) return;
    const int c = (int)(gt & 15);

    const int s = src[e];
    const int d = dst[e];
    const int r = ety[e];
    const float nm = norm[e];

    float4 v = ((const float4*)(Ht + ((size_t)r * NND + s) * DD))[c];
    v.x *= nm; v.y *= nm; v.z *= nm; v.w *= nm;

    float* q = out + (size_t)d * DD + (size_t)c * 4;
    asm volatile("red.global.add.v4.f32 [%0], {%1,%2,%3,%4};"
                 :: "l"(q), "f"(v.x), "f"(v.y), "f"(v.z), "f"(v.w)
                 : "memory");
}

// ----------------------------------------------------------------------------
// Decoder: rec[n] = (relu(henc[n] @ W1 + b1)) @ W2 + b2.  One warp per node.
// ----------------------------------------------------------------------------
__global__ void __launch_bounds__(256) decoder_kernel(
    const float* __restrict__ henc, const float* __restrict__ w1,
    const float* __restrict__ b1, const float* __restrict__ w2,
    const float* __restrict__ b2, float* __restrict__ rec)
{
    __shared__ float w1s[DD * DD];
    __shared__ float w2s[DD], b1s[DD];
    __shared__ float b2s;
    const int tid = threadIdx.x;
    for (int i = tid; i < DD * DD; i += 256) w1s[i] = w1[i];
    if (tid < DD) { w2s[tid] = w2[tid]; b1s[tid] = b1[tid]; }
    if (tid == 0) b2s = b2[0];
    __syncthreads();

    const int lane = tid & 31;
    const int w = tid >> 5;            // 8 warps per block
    for (int node = blockIdx.x * 8 + w; node < NND; node += gridDim.x * 8) {
        const float xa = henc[(size_t)node * DD + lane];
        const float xb = henc[(size_t)node * DD + 32 + lane];
        float s0 = b1s[lane], s1 = b1s[lane + 32];
        #pragma unroll
        for (int i = 0; i < 32; i++) {
            const float xi = __shfl_sync(0xffffffffu, xa, i);
            s0 += xi * w1s[i * DD + lane];
            s1 += xi * w1s[i * DD + lane + 32];
        }
        #pragma unroll
        for (int i = 0; i < 32; i++) {
            const float xi = __shfl_sync(0xffffffffu, xb, i);
            s0 += xi * w1s[(32 + i) * DD + lane];
            s1 += xi * w1s[(32 + i) * DD + lane + 32];
        }
        s0 = fmaxf(s0, 0.f); s1 = fmaxf(s1, 0.f);
        float v = s0 * w2s[lane] + s1 * w2s[lane + 32];
        #pragma unroll
        for (int off = 16; off; off >>= 1)
            v += __shfl_down_sync(0xffffffffu, v, off);
        if (lane == 0) rec[node] = v + b2s;
    }
}

// ----------------------------------------------------------------------------
extern "C" void kernel_launch(void* const* d_in, const int* in_sizes, int n_in,
                              void* d_out, int out_size)
{
    const float* h      = (const float*)d_in[0];
    const int*   src    = (const int*)  d_in[1];
    const int*   dst    = (const int*)  d_in[2];
    const int*   ety    = (const int*)  d_in[3];
    const float* norm   = (const float*)d_in[4];
    const float* bases0 = (const float*)d_in[5];
    const float* wcomp0 = (const float*)d_in[6];
    const float* bases1 = (const float*)d_in[7];
    const float* wcomp1 = (const float*)d_in[8];
    const float* bases2 = (const float*)d_in[9];
    const float* wcomp2 = (const float*)d_in[10];
    const float* dw1    = (const float*)d_in[11];
    const float* db1    = (const float*)d_in[12];
    const float* dw2    = (const float*)d_in[13];
    const float* db2    = (const float*)d_in[14];

    float* out  = (float*)d_out;
    float* rec  = out;                 // [N]
    float* henc = out + NND;           // [N, D]

    float *Ht, *h1, *h2;
    cudaGetSymbolAddress((void**)&Ht, g_Ht);
    cudaGetSymbolAddress((void**)&h1, g_h1);
    cudaGetSymbolAddress((void**)&h2, g_h2);

    const int SMEM_T = (BB * DD * DD + 64 * DD + 32) * sizeof(float);  // 82 KB
    cudaFuncSetAttribute(transform_kernel,
                         cudaFuncAttributeMaxDynamicSharedMemorySize, SMEM_T);

    const int TBLK = (NND + 63) / 64;                 // 1563
    const int EBLK = (int)(((long long)EE * 16 + 255) / 256);  // 100000

    // layer 1: h -> h1
    transform_kernel<<<TBLK, 256, SMEM_T>>>(h, bases0, wcomp0, Ht, 0);
    cudaMemsetAsync(h1, 0, (size_t)NND * DD * sizeof(float));
    edge_kernel<<<EBLK, 256>>>(Ht, src, dst, ety, norm, h1);

    // layer 2: relu(h1) -> h2
    transform_kernel<<<TBLK, 256, SMEM_T>>>(h1, bases1, wcomp1, Ht, 1);
    cudaMemsetAsync(h2, 0, (size_t)NND * DD * sizeof(float));
    edge_kernel<<<EBLK, 256>>>(Ht, src, dst, ety, norm, h2);

    // layer 3: relu(h2) -> henc (written straight into d_out, no activation)
    transform_kernel<<<TBLK, 256, SMEM_T>>>(h2, bases2, wcomp2, Ht, 1);
    cudaMemsetAsync(henc, 0, (size_t)NND * DD * sizeof(float));
    edge_kernel<<<EBLK, 256>>>(Ht, src, dst, ety, norm, henc);

    // decoder -> rec
    decoder_kernel<<<2048, 256>>>(henc, dw1, db1, dw2, db2, rec);
}

// round 2
// speedup vs baseline: 1.0673x; 1.0673x over previous
#include <cuda_runtime.h>
#include <cstddef>
#include <cstdint>

#define NND 100000
#define EE  1600000
#define RR  8
#define BB  4
#define DD  64
#define NBIN 512            // 8 relations x 64 src-range sub-bins
#define SUBSHIFT 11         // src >> 11  (100000 >> 11 = 48 < 64)

// Scratch (no runtime allocation allowed) ------------------------------------
__device__ float g_Ht[(size_t)RR * NND * DD];   // 204.8 MB transformed features
__device__ float g_h1[(size_t)NND * DD];        // layer-1 output
__device__ float g_h2[(size_t)NND * DD];        // layer-2 output

__device__ int   g_binCnt[NBIN];
__device__ int   g_binCur[NBIN];
__device__ int   g_prow[EE];     // etype*N + src, bucketed
__device__ int   g_pdst[EE];
__device__ float g_pnorm[EE];

// ---------------------------------------------------------------- f32x2 utils
__device__ __forceinline__ void fma2(unsigned long long& a,
                                     unsigned long long x,
                                     unsigned long long b) {
    asm("fma.rn.f32x2 %0, %1, %2, %0;" : "+l"(a) : "l"(x), "l"(b));
}
__device__ __forceinline__ unsigned long long dup2(float x) {
    unsigned long long r;
    asm("mov.b64 %0, {%1, %1};" : "=l"(r) : "f"(x));
    return r;
}

// ----------------------------------------------------------------------------
// Transform: Ht[r,n,o] = sum_b wcomp[r,b] * sum_i relu?(X[n,i]) * bases[b,i,o]
// FFMA2 version: each thread owns output pair o=(2*o2, 2*o2+1), 8 nodes.
// Block = 256 threads = (o2:32) x (q:8 node groups of 8). Tile = 64 nodes.
// ----------------------------------------------------------------------------
__global__ void __launch_bounds__(256) transform_kernel(
    const float* __restrict__ X, const float* __restrict__ bases,
    const float* __restrict__ wcomp, float* __restrict__ Ht, int relu)
{
    extern __shared__ float sm[];
    float* bs = sm;                    // 4*64*64 = 16384 floats
    float* xs = sm + BB * DD * DD;     // 64*64   = 4096 floats
    float* wc = xs + 64 * DD;          // 32 floats

    const int tid = threadIdx.x;

    // load bases into smem (vectorized)
    {
        const float4* b4 = (const float4*)bases;
        float4* s4 = (float4*)bs;
        #pragma unroll 4
        for (int i = tid; i < BB * DD * DD / 4; i += 256) s4[i] = b4[i];
    }
    if (tid < RR * BB) wc[tid] = wcomp[tid];

    // load node tile (with fused relu on input), zero-pad past N
    const int n0 = blockIdx.x * 64;
    for (int i = tid; i < 64 * DD / 4; i += 256) {
        int n = i / (DD / 4);
        float4 v = make_float4(0.f, 0.f, 0.f, 0.f);
        if (n0 + n < NND) {
            v = ((const float4*)X)[(size_t)(n0 + n) * (DD / 4) + (i % (DD / 4))];
            if (relu) {
                v.x = fmaxf(v.x, 0.f); v.y = fmaxf(v.y, 0.f);
                v.z = fmaxf(v.z, 0.f); v.w = fmaxf(v.w, 0.f);
            }
        }
        ((float4*)xs)[i] = v;
    }
    __syncthreads();

    const int o2 = tid & 31;           // output pair index, o = 2*o2
    const int q  = tid >> 5;           // node group 0..7 (8 nodes each)

    unsigned long long acc[BB][8];
    #pragma unroll
    for (int b = 0; b < BB; b++)
        #pragma unroll
        for (int n = 0; n < 8; n++) acc[b][n] = 0ull;

    const float* xb = xs + q * 8 * DD;

    #pragma unroll 4
    for (int i = 0; i < DD; i++) {
        const unsigned long long b0 =
            *(const unsigned long long*)(bs + 0 * DD * DD + i * DD + 2 * o2);
        const unsigned long long b1 =
            *(const unsigned long long*)(bs + 1 * DD * DD + i * DD + 2 * o2);
        const unsigned long long b2 =
            *(const unsigned long long*)(bs + 2 * DD * DD + i * DD + 2 * o2);
        const unsigned long long b3 =
            *(const unsigned long long*)(bs + 3 * DD * DD + i * DD + 2 * o2);
        #pragma unroll
        for (int n = 0; n < 8; n++) {
            const unsigned long long x2 = dup2(xb[n * DD + i]);  // warp-uniform
            fma2(acc[0][n], x2, b0);
            fma2(acc[1][n], x2, b1);
            fma2(acc[2][n], x2, b2);
            fma2(acc[3][n], x2, b3);
        }
    }

    // combine with wcomp and store all 8 relations (64-bit stores, coalesced)
    #pragma unroll
    for (int r = 0; r < RR; r++) {
        const unsigned long long w0 = dup2(wc[r * BB + 0]);
        const unsigned long long w1 = dup2(wc[r * BB + 1]);
        const unsigned long long w2 = dup2(wc[r * BB + 2]);
        const unsigned long long w3 = dup2(wc[r * BB + 3]);
        #pragma unroll
        for (int n = 0; n < 8; n++) {
            const int node = n0 + q * 8 + n;
            if (node >= NND) break;
            unsigned long long v = 0ull;
            fma2(v, w0, acc[0][n]);
            fma2(v, w1, acc[1][n]);
            fma2(v, w2, acc[2][n]);
            fma2(v, w3, acc[3][n]);
            *(unsigned long long*)(Ht + ((size_t)r * NND + node) * DD + 2 * o2) = v;
        }
    }
}

// ----------------------------------------------------------- edge bucketizing
__global__ void zero_bins_kernel() {
    int i = blockIdx.x * blockDim.x + threadIdx.x;
    if (i < NBIN) g_binCnt[i] = 0;
}

__global__ void __launch_bounds__(256) hist_kernel(
    const int* __restrict__ ety, const int* __restrict__ src)
{
    __shared__ int c[NBIN];
    for (int i = threadIdx.x; i < NBIN; i += 256) c[i] = 0;
    __syncthreads();
    for (long long e = (long long)blockIdx.x * 256 + threadIdx.x; e < EE;
         e += (long long)gridDim.x * 256) {
        int bin = ety[e] * 64 + (src[e] >> SUBSHIFT);
        atomicAdd(&c[bin], 1);
    }
    __syncthreads();
    for (int i = threadIdx.x; i < NBIN; i += 256)
        if (c[i]) atomicAdd(&g_binCnt[i], c[i]);
}

__global__ void scan_kernel() {     // 1 block, NBIN threads
    __shared__ int s[NBIN];
    const int t = threadIdx.x;
    const int my = g_binCnt[t];
    s[t] = my;
    __syncthreads();
    for (int off = 1; off < NBIN; off <<= 1) {
        int v = (t >= off) ? s[t - off] : 0;
        __syncthreads();
        s[t] += v;
        __syncthreads();
    }
    g_binCur[t] = s[t] - my;        // exclusive prefix
}

#define SC_EDGES 4096               // edges per scatter block (256 thr x 16)
__global__ void __launch_bounds__(256) scatter_kernel(
    const int* __restrict__ src, const int* __restrict__ dst,
    const int* __restrict__ ety, const float* __restrict__ norm)
{
    __shared__ int cnt[NBIN], base[NBIN];
    const int tid = threadIdx.x;
    const long long e0 = (long long)blockIdx.x * SC_EDGES;

    for (int i = tid; i < NBIN; i += 256) cnt[i] = 0;
    __syncthreads();

    int mybin[16], mysrc[16];
    #pragma unroll
    for (int k = 0; k < 16; k++) {
        long long e = e0 + tid + k * 256;
        if (e < EE) {
            int s = src[e];
            mysrc[k] = s;
            mybin[k] = ety[e] * 64 + (s >> SUBSHIFT);
            atomicAdd(&cnt[mybin[k]], 1);
        } else mybin[k] = -1;
    }
    __syncthreads();

    for (int i = tid; i < NBIN; i += 256) {
        int c = cnt[i];
        base[i] = c ? atomicAdd(&g_binCur[i], c) : 0;
    }
    __syncthreads();
    for (int i = tid; i < NBIN; i += 256) cnt[i] = 0;
    __syncthreads();

    #pragma unroll
    for (int k = 0; k < 16; k++) {
        if (mybin[k] < 0) continue;
        long long e = e0 + tid + k * 256;
        int loc = atomicAdd(&cnt[mybin[k]], 1);
        int pos = base[mybin[k]] + loc;
        g_prow[pos]  = (mybin[k] >> 6) * NND + mysrc[k];
        g_pdst[pos]  = dst[e];
        g_pnorm[pos] = norm[e];
    }
}

// ----------------------------------------------------------------------------
// Edge stage over bucketed edges: out[dst] += norm * Ht[rowid].
// 16 threads/edge, float4 lanes, red.v4 into L2-resident out.
// ----------------------------------------------------------------------------
__global__ void __launch_bounds__(256) edge_kernel(
    const float* __restrict__ Ht, const int* __restrict__ prow,
    const int* __restrict__ pdst, const float* __restrict__ pnorm,
    float* __restrict__ out)
{
    const long long gt = (long long)blockIdx.x * blockDim.x + threadIdx.x;
    const int e = (int)(gt >> 4);
    if (e >= EE) return;
    const int c = (int)(gt & 15);

    const int row  = prow[e];
    const int d    = pdst[e];
    const float nm = pnorm[e];

    float4 v = ((const float4*)(Ht + (size_t)row * DD))[c];
    v.x *= nm; v.y *= nm; v.z *= nm; v.w *= nm;

    float* q = out + (size_t)d * DD + (size_t)c * 4;
    asm volatile("red.global.add.v4.f32 [%0], {%1,%2,%3,%4};"
                 :: "l"(q), "f"(v.x), "f"(v.y), "f"(v.z), "f"(v.w)
                 : "memory");
}

// ----------------------------------------------------------------------------
// Decoder: rec[n] = (relu(henc[n] @ W1 + b1)) @ W2 + b2.  One warp per node.
// ----------------------------------------------------------------------------
__global__ void __launch_bounds__(256) decoder_kernel(
    const float* __restrict__ henc, const float* __restrict__ w1,
    const float* __restrict__ b1, const float* __restrict__ w2,
    const float* __restrict__ b2, float* __restrict__ rec)
{
    __shared__ float w1s[DD * DD];
    __shared__ float w2s[DD], b1s[DD];
    __shared__ float b2s;
    const int tid = threadIdx.x;
    for (int i = tid; i < DD * DD; i += 256) w1s[i] = w1[i];
    if (tid < DD) { w2s[tid] = w2[tid]; b1s[tid] = b1[tid]; }
    if (tid == 0) b2s = b2[0];
    __syncthreads();

    const int lane = tid & 31;
    const int w = tid >> 5;
    for (int node = blockIdx.x * 8 + w; node < NND; node += gridDim.x * 8) {
        const float xa = henc[(size_t)node * DD + lane];
        const float xb = henc[(size_t)node * DD + 32 + lane];
        float s0 = b1s[lane], s1 = b1s[lane + 32];
        #pragma unroll
        for (int i = 0; i < 32; i++) {
            const float xi = __shfl_sync(0xffffffffu, xa, i);
            s0 += xi * w1s[i * DD + lane];
            s1 += xi * w1s[i * DD + lane + 32];
        }
        #pragma unroll
        for (int i = 0; i < 32; i++) {
            const float xi = __shfl_sync(0xffffffffu, xb, i);
            s0 += xi * w1s[(32 + i) * DD + lane];
            s1 += xi * w1s[(32 + i) * DD + lane + 32];
        }
        s0 = fmaxf(s0, 0.f); s1 = fmaxf(s1, 0.f);
        float v = s0 * w2s[lane] + s1 * w2s[lane + 32];
        #pragma unroll
        for (int off = 16; off; off >>= 1)
            v += __shfl_down_sync(0xffffffffu, v, off);
        if (lane == 0) rec[node] = v + b2s;
    }
}

// ----------------------------------------------------------------------------
extern "C" void kernel_launch(void* const* d_in, const int* in_sizes, int n_in,
                              void* d_out, int out_size)
{
    const float* h      = (const float*)d_in[0];
    const int*   src    = (const int*)  d_in[1];
    const int*   dst    = (const int*)  d_in[2];
    const int*   ety    = (const int*)  d_in[3];
    const float* norm   = (const float*)d_in[4];
    const float* bases0 = (const float*)d_in[5];
    const float* wcomp0 = (const float*)d_in[6];
    const float* bases1 = (const float*)d_in[7];
    const float* wcomp1 = (const float*)d_in[8];
    const float* bases2 = (const float*)d_in[9];
    const float* wcomp2 = (const float*)d_in[10];
    const float* dw1    = (const float*)d_in[11];
    const float* db1    = (const float*)d_in[12];
    const float* dw2    = (const float*)d_in[13];
    const float* db2    = (const float*)d_in[14];

    float* out  = (float*)d_out;
    float* rec  = out;                 // [N]
    float* henc = out + NND;           // [N, D]

    float *Ht, *h1, *h2;
    int *prow, *pdst;
    float *pnorm;
    cudaGetSymbolAddress((void**)&Ht, g_Ht);
    cudaGetSymbolAddress((void**)&h1, g_h1);
    cudaGetSymbolAddress((void**)&h2, g_h2);
    cudaGetSymbolAddress((void**)&prow, g_prow);
    cudaGetSymbolAddress((void**)&pdst, g_pdst);
    cudaGetSymbolAddress((void**)&pnorm, g_pnorm);

    const int SMEM_T = (BB * DD * DD + 64 * DD + 32) * sizeof(float);  // ~82 KB
    cudaFuncSetAttribute(transform_kernel,
                         cudaFuncAttributeMaxDynamicSharedMemorySize, SMEM_T);

    const int TBLK = (NND + 63) / 64;                        // 1563
    const int EBLK = (int)(((long long)EE * 16 + 255) / 256);// 100000
    const int SBLK = (EE + SC_EDGES - 1) / SC_EDGES;         // 391

    // ---- bucketize edges by (etype, src-range): done once, reused 3x ----
    zero_bins_kernel<<<2, 256>>>();
    hist_kernel<<<1024, 256>>>(ety, src);
    scan_kernel<<<1, NBIN>>>();
    scatter_kernel<<<SBLK, 256>>>(src, dst, ety, norm);

    // layer 1: h -> h1
    transform_kernel<<<TBLK, 256, SMEM_T>>>(h, bases0, wcomp0, Ht, 0);
    cudaMemsetAsync(h1, 0, (size_t)NND * DD * sizeof(float));
    edge_kernel<<<EBLK, 256>>>(Ht, prow, pdst, pnorm, h1);

    // layer 2: relu(h1) -> h2
    transform_kernel<<<TBLK, 256, SMEM_T>>>(h1, bases1, wcomp1, Ht, 1);
    cudaMemsetAsync(h2, 0, (size_t)NND * DD * sizeof(float));
    edge_kernel<<<EBLK, 256>>>(Ht, prow, pdst, pnorm, h2);

    // layer 3: relu(h2) -> henc (written straight into d_out)
    transform_kernel<<<TBLK, 256, SMEM_T>>>(h2, bases2, wcomp2, Ht, 1);
    cudaMemsetAsync(henc, 0, (size_t)NND * DD * sizeof(float));
    edge_kernel<<<EBLK, 256>>>(Ht, prow, pdst, pnorm, henc);

    // decoder -> rec
    decoder_kernel<<<2048, 256>>>(henc, dw1, db1, dw2, db2, rec);
}

// round 4
// speedup vs baseline: 1.1904x; 1.1153x over previous
#include <cuda_runtime.h>
#include <cstddef>
#include <cstdint>

#define NND 100000
#define EE  1600000
#define RR  8
#define BB  4
#define DD  64

#define LBLK 512                 // threads per layer block
#define NODES_PB 128             // dst nodes per layer block
#define NLB ((NND + NODES_PB - 1) / NODES_PB)   // 782
#define NCH ((NND + 1023) / 1024)               // 98 scan chunks

// Scratch (no runtime allocation allowed) ------------------------------------
__device__ float g_h1[(size_t)NND * DD];
__device__ float g_h2[(size_t)NND * DD];
__device__ int   g_deg[NND];
__device__ int   g_rowptr[NND + 1];
__device__ int   g_cur[NND];
__device__ int   g_csum[NCH];
__device__ int   g_coff[NCH];
__device__ int   g_epack[EE];    // src | (ety<<20), CSR-ordered by dst
__device__ float g_enorm[EE];

// ---------------------------------------------------------------- f32x2 utils
typedef unsigned long long ull;
__device__ __forceinline__ void fma2(ull& a, ull x, ull b) {
    asm("fma.rn.f32x2 %0, %1, %2, %0;" : "+l"(a) : "l"(x), "l"(b));
}
__device__ __forceinline__ ull dup2(float x) {
    ull r; asm("mov.b64 %0, {%1, %1};" : "=l"(r) : "f"(x)); return r;
}
__device__ __forceinline__ float2 unp2(ull v) {
    float2 r; asm("mov.b64 {%0, %1}, %2;" : "=f"(r.x), "=f"(r.y) : "l"(v));
    return r;
}

// ----------------------------------------------------------------- CSR build
__global__ void __launch_bounds__(256) hist_kernel(const int* __restrict__ dst) {
    for (long long e = (long long)blockIdx.x * 256 + threadIdx.x; e < EE;
         e += (long long)gridDim.x * 256)
        atomicAdd(&g_deg[dst[e]], 1);
}

__global__ void __launch_bounds__(256) scan1_kernel() {   // grid NCH
    __shared__ int s[256];
    const int b = blockIdx.x, t = threadIdx.x;
    int v = 0;
    #pragma unroll
    for (int j = 0; j < 4; j++) {
        int i = b * 1024 + t * 4 + j;
        if (i < NND) v += g_deg[i];
    }
    s[t] = v; __syncthreads();
    for (int off = 128; off; off >>= 1) {
        if (t < off) s[t] += s[t + off];
        __syncthreads();
    }
    if (t == 0) g_csum[b] = s[0];
}

__global__ void __launch_bounds__(128) scan2_kernel() {   // 1 block
    __shared__ int s[128];
    const int t = threadIdx.x;
    const int my = (t < NCH) ? g_csum[t] : 0;
    s[t] = my; __syncthreads();
    for (int off = 1; off < 128; off <<= 1) {
        int x = (t >= off) ? s[t - off] : 0;
        __syncthreads();
        s[t] += x;
        __syncthreads();
    }
    if (t < NCH) g_coff[t] = s[t] - my;   // exclusive chunk offsets
    if (t == 0) g_rowptr[NND] = EE;
}

__global__ void __launch_bounds__(256) scan3_kernel() {   // grid NCH
    __shared__ int s[256];
    const int b = blockIdx.x, t = threadIdx.x;
    int v[4];
    #pragma unroll
    for (int j = 0; j < 4; j++) {
        int i = b * 1024 + t * 4 + j;
        v[j] = (i < NND) ? g_deg[i] : 0;
    }
    const int tot = v[0] + v[1] + v[2] + v[3];
    s[t] = tot; __syncthreads();
    for (int off = 1; off < 256; off <<= 1) {
        int x = (t >= off) ? s[t - off] : 0;
        __syncthreads();
        s[t] += x;
        __syncthreads();
    }
    int run = g_coff[b] + s[t] - tot;     // exclusive prefix for elem 0
    #pragma unroll
    for (int j = 0; j < 4; j++) {
        int i = b * 1024 + t * 4 + j;
        if (i < NND) { g_rowptr[i] = run; g_cur[i] = run; }
        run += v[j];
    }
}

__global__ void __launch_bounds__(256) csr_scatter_kernel(
    const int* __restrict__ src, const int* __restrict__ dst,
    const int* __restrict__ ety, const float* __restrict__ norm)
{
    for (long long e = (long long)blockIdx.x * 256 + threadIdx.x; e < EE;
         e += (long long)gridDim.x * 256) {
        const int d = dst[e];
        const int pos = atomicAdd(&g_cur[d], 1);
        g_epack[pos] = src[e] | (ety[e] << 20);
        g_enorm[pos] = norm[e];
    }
}

// ----------------------------------------------------------------------------
// Fused RGCN layer:
//  phase 1: per-dst basis-weighted aggregation  aggB[d,b,:] = sum_e c_b * X[src]
//           (CSR segments, register accumulators, zero atomics)
//  phase 2: out[d,:] = sum_b bases_b^T aggB[d,b,:]   (FFMA2 GEMM from smem)
// Block: 512 threads, 128 dst nodes. smem: bases 64KB + agg 128KB + wc.
// ----------------------------------------------------------------------------
__global__ void __launch_bounds__(LBLK, 1) layer_kernel(
    const float* __restrict__ Xin, const float* __restrict__ bases,
    const float* __restrict__ wcomp, const int* __restrict__ rowptr,
    const int* __restrict__ epack, const float* __restrict__ enorm,
    float* __restrict__ Out, int relu_out)
{
    extern __shared__ float sm[];
    float* bs   = sm;                          // 16384 floats
    float* aggs = sm + BB * DD * DD;           // 32768 floats
    float4* wc4 = (float4*)(sm + BB * DD * DD + NODES_PB * BB * DD);  // 8 float4

    const int tid = threadIdx.x;
    const int n0 = blockIdx.x * NODES_PB;

    // load bases + wcomp
    {
        const float4* b4 = (const float4*)bases;
        float4* s4 = (float4*)bs;
        #pragma unroll 2
        for (int i = tid; i < BB * DD * DD / 4; i += LBLK) s4[i] = b4[i];
    }
    if (tid < RR) wc4[tid] = ((const float4*)wcomp)[tid];
    __syncthreads();

    // ---- phase 1: edge aggregation, one warp per dst (8 dsts per warp) ----
    const int lane = tid & 31;
    const int w    = tid >> 5;                 // 16 warps

    for (int k = 0; k < 8; k++) {
        const int d = n0 + w * 8 + k;
        int beg = 0, end = 0;
        if (d < NND) { beg = rowptr[d]; end = rowptr[d + 1]; }

        ull a0 = 0, a1 = 0, a2 = 0, a3 = 0;
        int e = beg;
        for (; e + 8 <= end; e += 8) {
            int pk[8]; float nv[8];
            #pragma unroll
            for (int j = 0; j < 8; j++) pk[j] = __ldg(epack + e + j);
            #pragma unroll
            for (int j = 0; j < 8; j++) nv[j] = __ldg(enorm + e + j);
            ull xv[8];
            #pragma unroll
            for (int j = 0; j < 8; j++) {
                const int s = pk[j] & 0xFFFFF;
                xv[j] = *(const ull*)(Xin + (size_t)s * DD + 2 * lane);
            }
            #pragma unroll
            for (int j = 0; j < 8; j++) {
                const float4 wr = wc4[pk[j] >> 20];
                const float nm = nv[j];
                fma2(a0, dup2(wr.x * nm), xv[j]);
                fma2(a1, dup2(wr.y * nm), xv[j]);
                fma2(a2, dup2(wr.z * nm), xv[j]);
                fma2(a3, dup2(wr.w * nm), xv[j]);
            }
        }
        for (; e < end; e++) {
            const int pk = __ldg(epack + e);
            const float nm = __ldg(enorm + e);
            const int s = pk & 0xFFFFF;
            const ull xv = *(const ull*)(Xin + (size_t)s * DD + 2 * lane);
            const float4 wr = wc4[pk >> 20];
            fma2(a0, dup2(wr.x * nm), xv);
            fma2(a1, dup2(wr.y * nm), xv);
            fma2(a2, dup2(wr.z * nm), xv);
            fma2(a3, dup2(wr.w * nm), xv);
        }
        ull* ag = (ull*)(aggs + (w * 8 + k) * (BB * DD));
        ag[0 * 32 + lane] = a0;
        ag[1 * 32 + lane] = a1;
        ag[2 * 32 + lane] = a2;
        ag[3 * 32 + lane] = a3;
    }
    __syncthreads();

    // ---- phase 2: GEMM  out[n,o] = sum_{b,i} aggs[n,b,i] * bases[b,i,o] ----
    const int o4 = (tid & 15) * 4;             // output quad
    const int q  = tid >> 4;                   // 0..31, 4 nodes each

    ull acc[4][2];
    #pragma unroll
    for (int n = 0; n < 4; n++) { acc[n][0] = 0; acc[n][1] = 0; }

    const float* ab = aggs + q * 4 * (BB * DD);
    #pragma unroll
    for (int b = 0; b < BB; b++) {
        #pragma unroll 4
        for (int i = 0; i < DD; i++) {
            const float4 bv = *(const float4*)(bs + (b * DD + i) * DD + o4);
            const ull* bp = (const ull*)&bv;
            #pragma unroll
            for (int n = 0; n < 4; n++) {
                const ull x2 = dup2(ab[n * (BB * DD) + b * DD + i]);
                fma2(acc[n][0], x2, bp[0]);
                fma2(acc[n][1], x2, bp[1]);
            }
        }
    }

    #pragma unroll
    for (int n = 0; n < 4; n++) {
        const int node = n0 + q * 4 + n;
        if (node >= NND) continue;
        float2 lo = unp2(acc[n][0]);
        float2 hi = unp2(acc[n][1]);
        float4 o;
        if (relu_out) {
            o.x = fmaxf(lo.x, 0.f); o.y = fmaxf(lo.y, 0.f);
            o.z = fmaxf(hi.x, 0.f); o.w = fmaxf(hi.y, 0.f);
        } else {
            o.x = lo.x; o.y = lo.y; o.z = hi.x; o.w = hi.y;
        }
        *(float4*)(Out + (size_t)node * DD + o4) = o;
    }
}

// ----------------------------------------------------------------------------
// Decoder: rec[n] = (relu(henc[n] @ W1 + b1)) @ W2 + b2.  One warp per node.
// ----------------------------------------------------------------------------
__global__ void __launch_bounds__(256) decoder_kernel(
    const float* __restrict__ henc, const float* __restrict__ w1,
    const float* __restrict__ b1, const float* __restrict__ w2,
    const float* __restrict__ b2, float* __restrict__ rec)
{
    __shared__ float w1s[DD * DD];
    __shared__ float w2s[DD], b1s[DD];
    __shared__ float b2s;
    const int tid = threadIdx.x;
    for (int i = tid; i < DD * DD; i += 256) w1s[i] = w1[i];
    if (tid < DD) { w2s[tid] = w2[tid]; b1s[tid] = b1[tid]; }
    if (tid == 0) b2s = b2[0];
    __syncthreads();

    const int lane = tid & 31;
    const int w = tid >> 5;
    for (int node = blockIdx.x * 8 + w; node < NND; node += gridDim.x * 8) {
        const float xa = henc[(size_t)node * DD + lane];
        const float xb = henc[(size_t)node * DD + 32 + lane];
        float s0 = b1s[lane], s1 = b1s[lane + 32];
        #pragma unroll
        for (int i = 0; i < 32; i++) {
            const float xi = __shfl_sync(0xffffffffu, xa, i);
            s0 += xi * w1s[i * DD + lane];
            s1 += xi * w1s[i * DD + lane + 32];
        }
        #pragma unroll
        for (int i = 0; i < 32; i++) {
            const float xi = __shfl_sync(0xffffffffu, xb, i);
            s0 += xi * w1s[(32 + i) * DD + lane];
            s1 += xi * w1s[(32 + i) * DD + lane + 32];
        }
        s0 = fmaxf(s0, 0.f); s1 = fmaxf(s1, 0.f);
        float v = s0 * w2s[lane] + s1 * w2s[lane + 32];
        #pragma unroll
        for (int off = 16; off; off >>= 1)
            v += __shfl_down_sync(0xffffffffu, v, off);
        if (lane == 0) rec[node] = v + b2s;
    }
}

// ----------------------------------------------------------------------------
extern "C" void kernel_launch(void* const* d_in, const int* in_sizes, int n_in,
                              void* d_out, int out_size)
{
    const float* h      = (const float*)d_in[0];
    const int*   src    = (const int*)  d_in[1];
    const int*   dst    = (const int*)  d_in[2];
    const int*   ety    = (const int*)  d_in[3];
    const float* norm   = (const float*)d_in[4];
    const float* bases0 = (const float*)d_in[5];
    const float* wcomp0 = (const float*)d_in[6];
    const float* bases1 = (const float*)d_in[7];
    const float* wcomp1 = (const float*)d_in[8];
    const float* bases2 = (const float*)d_in[9];
    const float* wcomp2 = (const float*)d_in[10];
    const float* dw1    = (const float*)d_in[11];
    const float* db1    = (const float*)d_in[12];
    const float* dw2    = (const float*)d_in[13];
    const float* db2    = (const float*)d_in[14];

    float* out  = (float*)d_out;
    float* rec  = out;                 // [N]
    float* henc = out + NND;           // [N, D]

    float *h1, *h2, *enorm;
    int *deg, *rowptr, *epack;
    cudaGetSymbolAddress((void**)&h1, g_h1);
    cudaGetSymbolAddress((void**)&h2, g_h2);
    cudaGetSymbolAddress((void**)&deg, g_deg);
    cudaGetSymbolAddress((void**)&rowptr, g_rowptr);
    cudaGetSymbolAddress((void**)&epack, g_epack);
    cudaGetSymbolAddress((void**)&enorm, g_enorm);

    const int SMEM_L =
        (BB * DD * DD + NODES_PB * BB * DD + 32) * (int)sizeof(float); // ~196.7KB
    cudaFuncSetAttribute(layer_kernel,
                         cudaFuncAttributeMaxDynamicSharedMemorySize, SMEM_L);

    // ---- CSR by dst (once, reused 3x) ----
    cudaMemsetAsync(deg, 0, NND * sizeof(int));
    hist_kernel<<<1024, 256>>>(dst);
    scan1_kernel<<<NCH, 256>>>();
    scan2_kernel<<<1, 128>>>();
    scan3_kernel<<<NCH, 256>>>();
    csr_scatter_kernel<<<1024, 256>>>(src, dst, ety, norm);

    // ---- 3 fused RGCN layers ----
    layer_kernel<<<NLB, LBLK, SMEM_L>>>(h,  bases0, wcomp0, rowptr, epack, enorm, h1, 1);
    layer_kernel<<<NLB, LBLK, SMEM_L>>>(h1, bases1, wcomp1, rowptr, epack, enorm, h2, 1);
    layer_kernel<<<NLB, LBLK, SMEM_L>>>(h2, bases2, wcomp2, rowptr, epack, enorm, henc, 0);

    // ---- decoder ----
    decoder_kernel<<<2048, 256>>>(henc, dw1, db1, dw2, db2, rec);
}

// round 7
// speedup vs baseline: 1.2720x; 1.0686x over previous
#include <cuda_runtime.h>
#include <cstddef>
#include <cstdint>

#define NND 100000
#define EE  1600000
#define RR  8
#define BB  4
#define DD  64

#define LBLK 256                 // threads per layer block
#define NODES_PB 64              // dst nodes per layer block
#define NLB ((NND + NODES_PB - 1) / NODES_PB)   // 1563
#define NCH ((NND + 1023) / 1024)               // 98 scan chunks

typedef unsigned long long ull;
typedef unsigned int uint;

// Scratch (no runtime allocation allowed) ------------------------------------
__device__ float g_h1[(size_t)NND * DD];
__device__ float g_h2[(size_t)NND * DD];
__device__ int   g_deg[NND];
__device__ int   g_rowptr[NND + 1];
__device__ int   g_cur[NND];
__device__ int   g_csum[NCH];
__device__ int   g_coff[NCH];
__device__ ull   g_edata[EE];    // (norm bits << 32) | (ety << 20) | src

// ---------------------------------------------------------------- f32x2 utils
__device__ __forceinline__ void fma2(ull& a, ull x, ull b) {
    asm("fma.rn.f32x2 %0, %1, %2, %0;" : "+l"(a) : "l"(x), "l"(b));
}
__device__ __forceinline__ ull mul2(ull x, ull y) {
    ull r; asm("mul.rn.f32x2 %0, %1, %2;" : "=l"(r) : "l"(x), "l"(y)); return r;
}
__device__ __forceinline__ ull dup2(float x) {
    ull r; asm("mov.b64 %0, {%1, %1};" : "=l"(r) : "f"(x)); return r;
}
__device__ __forceinline__ float2 unp2(ull v) {
    float2 r; asm("mov.b64 {%0, %1}, %2;" : "=f"(r.x), "=f"(r.y) : "l"(v));
    return r;
}

// ------------------------------------------------------------- cp.async utils
__device__ __forceinline__ void cp16(void* smem_dst, const void* gmem_src) {
    const uint s = (uint)__cvta_generic_to_shared(smem_dst);   // FIXED (was bad asm)
    asm volatile("cp.async.cg.shared.global [%0], [%1], 16;"
                 :: "r"(s), "l"(gmem_src) : "memory");
}
__device__ __forceinline__ void cp_commit() {
    asm volatile("cp.async.commit_group;" ::: "memory");
}
template <int N>
__device__ __forceinline__ void cp_wait() {
    asm volatile("cp.async.wait_group %0;" :: "n"(N) : "memory");
}

// ----------------------------------------------------------------- CSR build
__global__ void __launch_bounds__(256) hist_kernel(const int* __restrict__ dst) {
    for (long long e = (long long)blockIdx.x * 256 + threadIdx.x; e < EE;
         e += (long long)gridDim.x * 256)
        atomicAdd(&g_deg[dst[e]], 1);
}

__global__ void __launch_bounds__(256) scan1_kernel() {   // grid NCH
    __shared__ int s[256];
    const int b = blockIdx.x, t = threadIdx.x;
    int v = 0;
    #pragma unroll
    for (int j = 0; j < 4; j++) {
        int i = b * 1024 + t * 4 + j;
        if (i < NND) v += g_deg[i];
    }
    s[t] = v; __syncthreads();
    for (int off = 128; off; off >>= 1) {
        if (t < off) s[t] += s[t + off];
        __syncthreads();
    }
    if (t == 0) g_csum[b] = s[0];
}

__global__ void __launch_bounds__(128) scan2_kernel() {   // 1 block
    __shared__ int s[128];
    const int t = threadIdx.x;
    const int my = (t < NCH) ? g_csum[t] : 0;
    s[t] = my; __syncthreads();
    for (int off = 1; off < 128; off <<= 1) {
        int x = (t >= off) ? s[t - off] : 0;
        __syncthreads();
        s[t] += x;
        __syncthreads();
    }
    if (t < NCH) g_coff[t] = s[t] - my;
    if (t == 0) g_rowptr[NND] = EE;
}

__global__ void __launch_bounds__(256) scan3_kernel() {   // grid NCH
    __shared__ int s[256];
    const int b = blockIdx.x, t = threadIdx.x;
    int v[4];
    #pragma unroll
    for (int j = 0; j < 4; j++) {
        int i = b * 1024 + t * 4 + j;
        v[j] = (i < NND) ? g_deg[i] : 0;
    }
    const int tot = v[0] + v[1] + v[2] + v[3];
    s[t] = tot; __syncthreads();
    for (int off = 1; off < 256; off <<= 1) {
        int x = (t >= off) ? s[t - off] : 0;
        __syncthreads();
        s[t] += x;
        __syncthreads();
    }
    int run = g_coff[b] + s[t] - tot;
    #pragma unroll
    for (int j = 0; j < 4; j++) {
        int i = b * 1024 + t * 4 + j;
        if (i < NND) { g_rowptr[i] = run; g_cur[i] = run; }
        run += v[j];
    }
}

__global__ void __launch_bounds__(256) csr_scatter_kernel(
    const int* __restrict__ src, const int* __restrict__ dst,
    const int* __restrict__ ety, const float* __restrict__ norm)
{
    for (long long e = (long long)blockIdx.x * 256 + threadIdx.x; e < EE;
         e += (long long)gridDim.x * 256) {
        const int d = dst[e];
        const int pos = atomicAdd(&g_cur[d], 1);
        const ull v = ((ull)__float_as_uint(norm[e]) << 32)
                    | (uint)(src[e] | (ety[e] << 20));
        g_edata[pos] = v;
    }
}

// ----------------------------------------------------------------------------
// Fused RGCN layer. 256 threads, 64 dst nodes, 2 blocks/SM.
//  phase 1: aggB[d,b,:] = sum_{e->d} wcomp[ety,b]*norm * X[src]   (-> smem)
//           dynamic row grab, fully predicated 8-edge batches (MLP=8 always)
//  phase 2: out[d,:] = sum_b bases_b^T aggB[d,b,:]
//           bases staged per-basis (16KB panels) via double-buffered cp.async
// smem: 2x4096 (panels) + 16384 (agg) + 64 (wc2) floats = 96.5 KB
// ----------------------------------------------------------------------------
__global__ void __launch_bounds__(LBLK, 2) layer_kernel(
    const float* __restrict__ Xin, const float* __restrict__ bases,
    const float* __restrict__ wcomp, const int* __restrict__ rowptr,
    const ull* __restrict__ edata, float* __restrict__ Out, int relu_out)
{
    extern __shared__ float sm[];
    float* buf0 = sm;                         // 4096 floats (one base panel)
    float* buf1 = sm + 4096;                  // 4096 floats
    float* aggs = sm + 8192;                  // 64 * 256 floats
    ull*   wc2  = (ull*)(sm + 8192 + 16384);  // 32 ull (wcomp dup'd to f32x2)
    __shared__ int rowctr;

    const int tid = threadIdx.x;
    const int n0 = blockIdx.x * NODES_PB;

    if (tid < RR * BB) wc2[tid] = dup2(wcomp[tid]);
    if (tid == 0) rowctr = 0;

    // prefetch base panels 0 and 1 (16KB each) behind phase 1
    #pragma unroll
    for (int j = 0; j < 4; j++)
        cp16(buf0 + (tid + j * LBLK) * 4, bases + 0 * DD * DD + (tid + j * LBLK) * 4);
    cp_commit();
    #pragma unroll
    for (int j = 0; j < 4; j++)
        cp16(buf1 + (tid + j * LBLK) * 4, bases + 1 * DD * DD + (tid + j * LBLK) * 4);
    cp_commit();

    __syncthreads();   // wc2 + rowctr visible

    // ---- phase 1 ----
    const int lane = tid & 31;
    while (true) {
        int k;
        if (lane == 0) k = atomicAdd(&rowctr, 1);
        k = __shfl_sync(0xffffffffu, k, 0);
        if (k >= NODES_PB) break;
        const int d = n0 + k;
        if (d >= NND) continue;

        const int beg = rowptr[d];
        const int end = rowptr[d + 1];

        ull a0 = 0, a1 = 0, a2 = 0, a3 = 0;
        for (int e = beg; e < end; e += 8) {
            ull ed[8];
            #pragma unroll
            for (int j = 0; j < 8; j++) {
                const int idx = (e + j < end) ? e + j : end - 1;
                ed[j] = __ldg(edata + idx);
            }
            ull xv[8];
            #pragma unroll
            for (int j = 0; j < 8; j++) {
                const int s = (uint)ed[j] & 0xFFFFF;
                xv[j] = *(const ull*)(Xin + (size_t)s * DD + 2 * lane);
            }
            #pragma unroll
            for (int j = 0; j < 8; j++) {
                float nm = __uint_as_float((uint)(ed[j] >> 32));
                if (e + j >= end) nm = 0.f;        // predicated tail
                const int r = ((uint)ed[j] >> 20) & 7;
                const ull xnm = mul2(xv[j], dup2(nm));
                fma2(a0, wc2[r * 4 + 0], xnm);
                fma2(a1, wc2[r * 4 + 1], xnm);
                fma2(a2, wc2[r * 4 + 2], xnm);
                fma2(a3, wc2[r * 4 + 3], xnm);
            }
        }
        ull* ag = (ull*)(aggs + k * (BB * DD));
        ag[0 * 32 + lane] = a0;
        ag[1 * 32 + lane] = a1;
        ag[2 * 32 + lane] = a2;
        ag[3 * 32 + lane] = a3;
    }

    // ---- phase 2 ----
    const int o4 = (tid & 15) * 4;            // output quad
    const int q  = tid >> 4;                  // 0..15, 4 nodes each

    ull acc[4][2];
    #pragma unroll
    for (int n = 0; n < 4; n++) { acc[n][0] = 0; acc[n][1] = 0; }

    #pragma unroll
    for (int b = 0; b < BB; b++) {
        if (b < BB - 1) cp_wait<1>(); else cp_wait<0>();
        __syncthreads();                      // panel b ready + aggs visible

        const float* bb = (b & 1) ? buf1 : buf0;
        const float* ab = aggs + q * 4 * (BB * DD) + b * DD;

        #pragma unroll 4
        for (int i = 0; i < DD; i++) {
            const float4 bv = *(const float4*)(bb + i * DD + o4);
            const ull* bp = (const ull*)&bv;
            #pragma unroll
            for (int n = 0; n < 4; n++) {
                const ull x2 = dup2(ab[n * (BB * DD) + i]);
                fma2(acc[n][0], x2, bp[0]);
                fma2(acc[n][1], x2, bp[1]);
            }
        }
        __syncthreads();                      // done reading panel b
        if (b + 2 < BB) {
            float* dstb = (b & 1) ? buf1 : buf0;
            #pragma unroll
            for (int j = 0; j < 4; j++)
                cp16(dstb + (tid + j * LBLK) * 4,
                     bases + (b + 2) * DD * DD + (tid + j * LBLK) * 4);
            cp_commit();
        }
    }

    #pragma unroll
    for (int n = 0; n < 4; n++) {
        const int node = n0 + q * 4 + n;
        if (node >= NND) continue;
        const float2 lo = unp2(acc[n][0]);
        const float2 hi = unp2(acc[n][1]);
        float4 o;
        if (relu_out) {
            o.x = fmaxf(lo.x, 0.f); o.y = fmaxf(lo.y, 0.f);
            o.z = fmaxf(hi.x, 0.f); o.w = fmaxf(hi.y, 0.f);
        } else {
            o.x = lo.x; o.y = lo.y; o.z = hi.x; o.w = hi.y;
        }
        *(float4*)(Out + (size_t)node * DD + o4) = o;
    }
}

// ----------------------------------------------------------------------------
// Decoder: rec[n] = (relu(henc[n] @ W1 + b1)) @ W2 + b2.  One warp per node.
// ----------------------------------------------------------------------------
__global__ void __launch_bounds__(256) decoder_kernel(
    const float* __restrict__ henc, const float* __restrict__ w1,
    const float* __restrict__ b1, const float* __restrict__ w2,
    const float* __restrict__ b2, float* __restrict__ rec)
{
    __shared__ float w1s[DD * DD];
    __shared__ float w2s[DD], b1s[DD];
    __shared__ float b2s;
    const int tid = threadIdx.x;
    for (int i = tid; i < DD * DD; i += 256) w1s[i] = w1[i];
    if (tid < DD) { w2s[tid] = w2[tid]; b1s[tid] = b1[tid]; }
    if (tid == 0) b2s = b2[0];
    __syncthreads();

    const int lane = tid & 31;
    const int w = tid >> 5;
    for (int node = blockIdx.x * 8 + w; node < NND; node += gridDim.x * 8) {
        const float xa = henc[(size_t)node * DD + lane];
        const float xb = henc[(size_t)node * DD + 32 + lane];
        float s0 = b1s[lane], s1 = b1s[lane + 32];
        #pragma unroll
        for (int i = 0; i < 32; i++) {
            const float xi = __shfl_sync(0xffffffffu, xa, i);
            s0 += xi * w1s[i * DD + lane];
            s1 += xi * w1s[i * DD + lane + 32];
        }
        #pragma unroll
        for (int i = 0; i < 32; i++) {
            const float xi = __shfl_sync(0xffffffffu, xb, i);
            s0 += xi * w1s[(32 + i) * DD + lane];
            s1 += xi * w1s[(32 + i) * DD + lane + 32];
        }
        s0 = fmaxf(s0, 0.f); s1 = fmaxf(s1, 0.f);
        float v = s0 * w2s[lane] + s1 * w2s[lane + 32];
        #pragma unroll
        for (int off = 16; off; off >>= 1)
            v += __shfl_down_sync(0xffffffffu, v, off);
        if (lane == 0) rec[node] = v + b2s;
    }
}

// ----------------------------------------------------------------------------
extern "C" void kernel_launch(void* const* d_in, const int* in_sizes, int n_in,
                              void* d_out, int out_size)
{
    const float* h      = (const float*)d_in[0];
    const int*   src    = (const int*)  d_in[1];
    const int*   dst    = (const int*)  d_in[2];
    const int*   ety    = (const int*)  d_in[3];
    const float* norm   = (const float*)d_in[4];
    const float* bases0 = (const float*)d_in[5];
    const float* wcomp0 = (const float*)d_in[6];
    const float* bases1 = (const float*)d_in[7];
    const float* wcomp1 = (const float*)d_in[8];
    const float* bases2 = (const float*)d_in[9];
    const float* wcomp2 = (const float*)d_in[10];
    const float* dw1    = (const float*)d_in[11];
    const float* db1    = (const float*)d_in[12];
    const float* dw2    = (const float*)d_in[13];
    const float* db2    = (const float*)d_in[14];

    float* out  = (float*)d_out;
    float* rec  = out;                 // [N]
    float* henc = out + NND;           // [N, D]

    float *h1, *h2;
    int *deg, *rowptr;
    ull *edata;
    cudaGetSymbolAddress((void**)&h1, g_h1);
    cudaGetSymbolAddress((void**)&h2, g_h2);
    cudaGetSymbolAddress((void**)&deg, g_deg);
    cudaGetSymbolAddress((void**)&rowptr, g_rowptr);
    cudaGetSymbolAddress((void**)&edata, g_edata);

    const int SMEM_L = (2 * DD * DD + NODES_PB * BB * DD + 64) * (int)sizeof(float);
    cudaFuncSetAttribute(layer_kernel,
                         cudaFuncAttributeMaxDynamicSharedMemorySize, SMEM_L);

    // ---- CSR by dst (once, reused 3x) ----
    cudaMemsetAsync(deg, 0, NND * sizeof(int));
    hist_kernel<<<1024, 256>>>(dst);
    scan1_kernel<<<NCH, 256>>>();
    scan2_kernel<<<1, 128>>>();
    scan3_kernel<<<NCH, 256>>>();
    csr_scatter_kernel<<<1024, 256>>>(src, dst, ety, norm);

    // ---- 3 fused RGCN layers ----
    layer_kernel<<<NLB, LBLK, SMEM_L>>>(h,  bases0, wcomp0, rowptr, edata, h1, 1);
    layer_kernel<<<NLB, LBLK, SMEM_L>>>(h1, bases1, wcomp1, rowptr, edata, h2, 1);
    layer_kernel<<<NLB, LBLK, SMEM_L>>>(h2, bases2, wcomp2, rowptr, edata, henc, 0);

    // ---- decoder ----
    decoder_kernel<<<2048, 256>>>(henc, dw1, db1, dw2, db2, rec);
}